// round 16
// baseline (speedup 1.0000x reference)
#include <cuda_runtime.h>
#include <cuda_bf16.h>
#include <cuda_fp16.h>
#include <cstdint>

#define TOK 131072
#define SCENES 16384
#define NL 4

#if !defined(__CUDA_ARCH__) || defined(__CUDA_ARCH_FEAT_SM103_ALL) || \
    defined(__CUDA_ARCH_FEAT_SM100_ALL) || defined(__CUDA_ARCH_FEAT_SM101_ALL) || \
    defined(__CUDA_ARCH_FEAT_SM110_ALL) || defined(__CUDA_ARCH_FEAT_SM120_ALL)
#define HAS_TC 1
#else
#define HAS_TC 0
#endif

__device__ float  g_x[(size_t)TOK * 256];
__device__ __half g_qkv[(size_t)TOK * 768];
__device__ __half g_o[(size_t)TOK * 256];
__device__ float  g_bias[(size_t)NL * SCENES * 8 * 64];
__device__ float  g_rs[TOK];
__device__ int    g_alive_u8;
__device__ __half g_wblob[(size_t)34 * 4 * 2 * 8192];
__device__ float  g_Wc[64 * 32];
__device__ float  g_bc[32];
__device__ float  g_bqkv[NL * 768];

__device__ __forceinline__ unsigned long long fma2(unsigned long long a,
                                                   unsigned long long b,
                                                   unsigned long long c) {
    unsigned long long d;
    asm("fma.rn.f32x2 %0, %1, %2, %3;" : "=l"(d) : "l"(a), "l"(b), "l"(c));
    return d;
}
__device__ __forceinline__ unsigned long long dup2(float x) {
    unsigned long long r; asm("mov.b64 %0, {%1, %1};" : "=l"(r) : "f"(x)); return r;
}
__device__ __forceinline__ unsigned long long pk2(float a, float b) {
    unsigned long long r; asm("mov.b64 %0, {%1, %2};" : "=l"(r) : "f"(a), "f"(b)); return r;
}
__device__ __forceinline__ float2 unp2(unsigned long long v) {
    float2 r; asm("mov.b64 {%0, %1}, %2;" : "=f"(r.x), "=f"(r.y) : "l"(v)); return r;
}
__device__ __forceinline__ uint32_t smem_u32(const void* p) {
    uint32_t a;
    asm("{ .reg .u64 t; cvta.to.shared.u64 t, %1; cvt.u32.u64 %0, t; }" : "=r"(a) : "l"(p));
    return a;
}
__device__ __forceinline__ bool aget(const unsigned char* a, int i) {
    return g_alive_u8 ? (a[i] != 0) : (a[i * 4] != 0);
}
__device__ __forceinline__ uint32_t sw_off(int row, int kl) {
    uint32_t b = (row & 7) * 128 + kl * 2;
    b ^= (b >> 3) & 0x70;
    return (uint32_t)((row >> 3) * 1024) + b;
}
#define MMA_IDESC 0x8200010u

#if HAS_TC
#define MBAR_WAIT(mba, par) do { \
    uint32_t _m = (mba); uint32_t _p = (par); uint32_t _d; \
    asm volatile("{\n\t.reg .pred p;\n\tmbarrier.try_wait.parity.acquire.cta.shared::cta.b64 p, [%1], %2;\n\tselp.b32 %0, 1, 0, p;\n\t}" \
        : "=r"(_d) : "r"(_m), "r"(_p) : "memory"); \
    if (!_d) { \
        asm volatile("{\n\t.reg .pred P1;\n\tWL_%=:\n\tmbarrier.try_wait.parity.acquire.cta.shared::cta.b64 P1, [%0], %1, 0x989680;\n\t@P1 bra.uni WD_%=;\n\tbra.uni WL_%=;\n\tWD_%=:\n\t}" \
            :: "r"(_m), "r"(_p) : "memory"); \
    } } while (0)
#endif

__global__ void detect_k(const unsigned char* __restrict__ a) {
    __shared__ int any;
    if (threadIdx.x == 0) any = 0;
    __syncthreads();
    for (int i = threadIdx.x; i < 4096; i += 256)
        if ((i & 3) != 0 && a[i] != 0) any = 1;
    __syncthreads();
    if (threadIdx.x == 0) g_alive_u8 = any;
}

__global__ void __launch_bounds__(256) enc1_k(const float* __restrict__ state,
                                              const unsigned char* __restrict__ alive,
                                              const float* __restrict__ dead,
                                              const float* __restrict__ W1,
                                              const float* __restrict__ b1) {
    __shared__ float ss[32 * 16];
    const int tid = threadIdx.x;
    const int tokBase = blockIdx.x * 32;
#pragma unroll
    for (int r = 0; r < 2; r++) {
        int idx = tid * 2 + r;
        int t = idx >> 4, k = idx & 15;
        ss[idx] = aget(alive, tokBase + t) ? state[(size_t)(tokBase + t) * 16 + k] : dead[k];
    }
    __syncthreads();
    float w[16];
#pragma unroll
    for (int k = 0; k < 16; k++) w[k] = W1[k * 256 + tid];
    const float bc = b1[tid];
#pragma unroll 4
    for (int t = 0; t < 32; t++) {
        float a = bc;
#pragma unroll
        for (int k = 0; k < 16; k++) a += ss[t * 16 + k] * w[k];
        a = a / (1.0f + __expf(-a));
        g_o[(size_t)(tokBase + t) * 256 + tid] = __float2half(a);
    }
}

__global__ void __launch_bounds__(256) wconv_k(
    const float* __restrict__ encW2, const float* __restrict__ Wq,
    const float* __restrict__ Wk, const float* __restrict__ Wv,
    const float* __restrict__ Wo, const float* __restrict__ norm_w,
    __half* __restrict__ blob) {
    int gid = blockIdx.x * 256 + threadIdx.x;
    int region = gid >> 13;
    int r = gid & 8191;
    int nl = r >> 6, kl = r & 63;
    int tile = region >> 2, chunk = region & 3;
    int k = chunk * 64 + kl;
    const float* W; int n; float g = 1.0f;
    if (tile < 2) { W = encW2; n = tile * 128 + nl; }
    else {
        int t2 = tile - 2, l = t2 >> 3, j = t2 & 7;
        if (j < 6) {
            W = (j < 2 ? Wq : (j < 4 ? Wk : Wv)) + l * 65536;
            n = (j & 1) * 128 + nl;
            g = norm_w[l * 256 + k];
        } else { W = Wo + l * 65536; n = (j - 6) * 128 + nl; }
    }
    float w = W[k * 256 + n] * g;
    __half hi = __float2half_rn(w);
    __half lo = __float2half_rn(w - __half2float(hi));
    uint32_t b = (nl & 7) * 128 + kl * 2; b ^= (b >> 3) & 0x70;
    uint32_t eo = (uint32_t)((nl >> 3) * 512) + (b >> 1);
    size_t base = (size_t)region * 2 * 8192;
    blob[base + eo] = hi;
    blob[base + 8192 + eo] = lo;
}

__global__ void packb_k(const float* __restrict__ bq, const float* __restrict__ bk,
                        const float* __restrict__ bv, float* __restrict__ dst) {
    int gid = blockIdx.x * 256 + threadIdx.x;
    if (gid >= NL * 768) return;
    int l = gid / 768, c = gid - l * 768;
    float v = c < 256 ? bq[l * 256 + c] : (c < 512 ? bk[l * 256 + c - 256] : bv[l * 256 + c - 512]);
    dst[gid] = v;
}

__global__ void __launch_bounds__(256) fold_k(const float* __restrict__ tW2,
                                              const float* __restrict__ aW,
                                              const float* __restrict__ tb2,
                                              const float* __restrict__ ab) {
    int tid = threadIdx.x;
#pragma unroll
    for (int i = 0; i < 8; i++) {
        int idx = tid + i * 256;
        int k = idx >> 5, m = idx & 31, l = m >> 3, h = m & 7;
        float s = 0.f;
        for (int c = 0; c < 64; c++) s += tW2[k * 64 + c] * aW[(l * 64 + c) * 8 + h];
        g_Wc[idx] = s;
    }
    if (tid < 32) {
        int l = tid >> 3, h = tid & 7;
        float s = ab[tid];
        for (int c = 0; c < 64; c++) s += tb2[c] * aW[(l * 64 + c) * 8 + h];
        g_bc[tid] = s;
    }
}

// tcgen05 GEMM. NT = # of 128-wide N tiles per CTA (2: occ2; 1: occ4).
#define SMEMB2 102400
#define SMEMB1 51200
template <int AIN, int AMODE, int EMODE, int RMSOUT, int COUT, int SWAP, int ATTN, int NT>
__global__ void __launch_bounds__(256, (NT == 1 ? 4 : 2)) mm_k(
    const void* __restrict__ Av, const __half* __restrict__ blob, int tileBase,
    const float* __restrict__ bias, void* __restrict__ Cv, int ldc,
    const float* __restrict__ rscale, float* __restrict__ rsout,
    const float* __restrict__ team_emb, const float* __restrict__ ship_emb,
    const int* __restrict__ team_ids,
    const float* __restrict__ abias, const unsigned char* __restrict__ alivep) {
#if HAS_TC
    extern __shared__ char dsm_raw[];
    char* sm = (char*)(((uintptr_t)dsm_raw + 1023) & ~(uintptr_t)1023);
    const uint32_t sbase = smem_u32(sm);
    const int tid = threadIdx.x, wid = tid >> 5, lane = tid & 31;
    const int rowTile = SWAP ? blockIdx.y : blockIdx.x;
    const int ntile = SWAP ? blockIdx.x : blockIdx.y;
    const int rowBase = rowTile * 128;
    const int coff = ntile * (NT * 128);
    const uint32_t AOFF = NT * 32768;           // B region first, then A (16KB)
    const uint32_t ctrl = sbase + AOFF + 16384;
    const uint32_t mbar = ctrl + 8;

    if (wid == 0) {
        asm volatile("tcgen05.alloc.cta_group::1.sync.aligned.shared::cta.b32 [%0], %1;"
                     :: "r"(ctrl), "r"(NT * 128) : "memory");
        asm volatile("tcgen05.relinquish_alloc_permit.cta_group::1.sync.aligned;");
    }
    if (tid == 0)
        asm volatile("mbarrier.init.shared.b64 [%0], %1;" :: "r"(mbar), "r"(1) : "memory");
    __syncthreads();
    const uint32_t tmem = *(volatile uint32_t*)(sm + AOFF + 16384);

    const int arow = tid >> 1, klb = (tid & 1) * 32;
    float rsv = 1.0f;
    if (AMODE == 1) rsv = rscale[rowBase + arow];
    const float* Apf = (const float*)Av + (size_t)(rowBase + arow) * 256 + klb;
    const __half* Aph = (const __half*)Av + (size_t)(rowBase + arow) * 256 + klb;
    const int pairq = tid >> 3, sub = tid & 7;
    const int sc16 = pairq >> 1, hsel = pairq & 1;
    const int scene = rowTile * 16 + sc16;
    const int tok = scene * 8 + sub;
    const int shsrc = (lane & 24);

    for (int c = 0; c < 4; c++) {
        if (c > 0) MBAR_WAIT(mbar, (c - 1) & 1);
        // B: cp.async (NT*2 buffers of 16KB)
#pragma unroll
        for (int r = 0; r < NT * 2; r++) {
            int tile = NT == 2 ? (tileBase + ntile * 2 + (r >> 1)) : (tileBase + ntile);
            int hilo = NT == 2 ? (r & 1) : r;
            const char* srcb = (const char*)(blob + (size_t)((tile * 4 + c) * 2 + hilo) * 8192);
#pragma unroll
            for (int j = 0; j < 4; j++) {
                uint32_t d = sbase + (uint32_t)(r * 16384) + (uint32_t)((tid + j * 256) * 16);
                asm volatile("cp.async.cg.shared.global [%0], [%1], 16;"
                             :: "r"(d), "l"(srcb + (tid + j * 256) * 16) : "memory");
            }
        }
        asm volatile("cp.async.commit_group;" ::: "memory");
        // A produce
        if (ATTN) {
            const __half* bq = (const __half*)Av + (size_t)tok * 768 + c * 64 + hsel * 32;
            float a8[8];
            {
                uint32_t qu[16], ku[16];
#pragma unroll
                for (int u = 0; u < 4; u++) {
                    uint4 a = *(const uint4*)(bq + u * 8);
                    uint4 b = *(const uint4*)(bq + 256 + u * 8);
                    qu[4 * u] = a.x; qu[4 * u + 1] = a.y; qu[4 * u + 2] = a.z; qu[4 * u + 3] = a.w;
                    ku[4 * u] = b.x; ku[4 * u + 1] = b.y; ku[4 * u + 2] = b.z; ku[4 * u + 3] = b.w;
                }
                const float* bp = abias + (((size_t)scene * 8) + (2 * c + hsel)) * 64 + sub * 8;
                float4 b0 = *(const float4*)bp, b1 = *(const float4*)(bp + 4);
                float brow[8] = {b0.x, b0.y, b0.z, b0.w, b1.x, b1.y, b1.z, b1.w};
#pragma unroll
                for (int jj = 0; jj < 8; jj++) {
                    float s = 0.f;
                    int src = shsrc | jj;
#pragma unroll
                    for (int d = 0; d < 16; d++) {
                        uint32_t kw = __shfl_sync(0xffffffffu, ku[d], src);
                        float2 kf = __half22float2(*(__half2*)&kw);
                        float2 qf = __half22float2(*(__half2*)&qu[d]);
                        s += qf.x * kf.x + qf.y * kf.y;
                    }
                    a8[jj] = s * 0.17677669529663687f + brow[jj];
                    if (!aget(alivep, scene * 8 + jj)) a8[jj] = -1e9f;
                }
            }
            {
                float m = a8[0];
#pragma unroll
                for (int jj = 1; jj < 8; jj++) m = fmaxf(m, a8[jj]);
                float tot = 0.f;
#pragma unroll
                for (int jj = 0; jj < 8; jj++) { a8[jj] = __expf(a8[jj] - m); tot += a8[jj]; }
                float inv = 1.0f / tot;
#pragma unroll
                for (int jj = 0; jj < 8; jj++) a8[jj] *= inv;
            }
            const int row = sc16 * 8 + sub;
#pragma unroll
            for (int vh = 0; vh < 2; vh++) {
                uint32_t vu[8];
                const __half* bv = bq + 512 + vh * 16;
#pragma unroll
                for (int u = 0; u < 2; u++) {
                    uint4 d = *(const uint4*)(bv + u * 8);
                    vu[4 * u] = d.x; vu[4 * u + 1] = d.y; vu[4 * u + 2] = d.z; vu[4 * u + 3] = d.w;
                }
                float o16[16];
#pragma unroll
                for (int d = 0; d < 16; d++) o16[d] = 0.f;
#pragma unroll
                for (int jj = 0; jj < 8; jj++) {
                    float a = a8[jj];
                    int src = shsrc | jj;
#pragma unroll
                    for (int d = 0; d < 8; d++) {
                        uint32_t vw = __shfl_sync(0xffffffffu, vu[d], src);
                        float2 vf = __half22float2(*(__half2*)&vw);
                        o16[2 * d] += a * vf.x;
                        o16[2 * d + 1] += a * vf.y;
                    }
                }
#pragma unroll
                for (int d8 = 0; d8 < 2; d8++) {
                    int kl = hsel * 32 + vh * 16 + d8 * 8;
                    __half2 p0 = __float22half2_rn(make_float2(o16[8 * d8], o16[8 * d8 + 1]));
                    __half2 p1 = __float22half2_rn(make_float2(o16[8 * d8 + 2], o16[8 * d8 + 3]));
                    __half2 p2 = __float22half2_rn(make_float2(o16[8 * d8 + 4], o16[8 * d8 + 5]));
                    __half2 p3 = __float22half2_rn(make_float2(o16[8 * d8 + 6], o16[8 * d8 + 7]));
                    *(uint4*)(sm + AOFF + sw_off(row, kl)) =
                        make_uint4(*(uint32_t*)&p0, *(uint32_t*)&p1, *(uint32_t*)&p2, *(uint32_t*)&p3);
                }
            }
        } else if (AIN == 1) {
            const uint4* ah4 = (const uint4*)(Aph + c * 64);
#pragma unroll
            for (int u = 0; u < 4; u++)
                *(uint4*)(sm + AOFF + sw_off(arow, klb + u * 8)) = ah4[u];
        } else {
            const float4* ap4 = (const float4*)(Apf + c * 64);
#pragma unroll
            for (int i = 0; i < 4; i++) {
                float4 lo4 = ap4[2 * i], hi4 = ap4[2 * i + 1];
                __half2 p0 = __float22half2_rn(make_float2(lo4.x * rsv, lo4.y * rsv));
                __half2 p1 = __float22half2_rn(make_float2(lo4.z * rsv, lo4.w * rsv));
                __half2 p2 = __float22half2_rn(make_float2(hi4.x * rsv, hi4.y * rsv));
                __half2 p3 = __float22half2_rn(make_float2(hi4.z * rsv, hi4.w * rsv));
                *(uint4*)(sm + AOFF + sw_off(arow, klb + i * 8)) =
                    make_uint4(*(uint32_t*)&p0, *(uint32_t*)&p1, *(uint32_t*)&p2, *(uint32_t*)&p3);
            }
        }
        asm volatile("cp.async.wait_group 0;" ::: "memory");
        asm volatile("fence.proxy.async.shared::cta;" ::: "memory");
        __syncthreads();
        if (wid == 0) {
            asm volatile("tcgen05.fence::after_thread_sync;" ::: "memory");
            uint32_t is_el;
            asm volatile("{\n\t.reg .pred p;\n\telect.sync _|p, 0xFFFFFFFF;\n\tselp.b32 %0, 1, 0, p;\n\t}" : "=r"(is_el));
            if (is_el) {
                const uint64_t DBASE = (2ull << 61) | (1ull << 46) | (64ull << 32) | (1ull << 16);
                uint64_t dA = DBASE | (((uint64_t)((sbase + AOFF) >> 4)) & 0x3FFF);
#pragma unroll
                for (int pass = 0; pass < 2; pass++) {
#pragma unroll
                    for (int t = 0; t < NT; t++) {
                        int bufi = NT == 2 ? (t * 2 + pass) : pass;
                        uint64_t bd = DBASE | (((uint64_t)((sbase + bufi * 16384) >> 4)) & 0x3FFF);
#pragma unroll
                        for (int ks = 0; ks < 4; ks++) {
                            uint32_t en = !(c == 0 && pass == 0 && ks == 0) ? 1u : 0u;
                            asm volatile(
                                "{\n\t.reg .pred p;\n\tsetp.ne.u32 p, %4, 0;\n\t"
                                "tcgen05.mma.cta_group::1.kind::f16 [%0], %1, %2, %3, {%5,%5,%5,%5}, p;\n\t}"
                                :: "r"(tmem + t * 128), "l"(dA + ks * 2), "l"(bd + ks * 2),
                                   "r"(MMA_IDESC), "r"(en), "r"(0u) : "memory");
                        }
                    }
                }
                asm volatile("tcgen05.commit.cta_group::1.mbarrier::arrive::one.shared::cluster.b64 [%0];"
                             :: "r"(mbar) : "memory");
            }
        }
    }
    MBAR_WAIT(mbar, 1);
    asm volatile("tcgen05.fence::after_thread_sync;" ::: "memory");

    const int ew = wid & 3, half = wid >> 2;
    const int rowl = ew * 32 + lane;
    const int grow = rowBase + rowl;
    float ss = 0.f;
    int tv = 0;
    if (EMODE == 1) tv = team_ids[grow];
    for (int it = 0; it < NT * 2; it++) {
        const int lc0 = half * (NT * 64) + it * 32;
        const int col0 = coff + lc0;
        float4 res[8];
        if (EMODE == 2) {
            const float4* rp = (const float4*)((const float*)Cv + (size_t)grow * ldc + col0);
#pragma unroll
            for (int q = 0; q < 8; q++) res[q] = rp[q];
        }
        float4 eb[8];
        if (EMODE == 1) {
            const float4* te = (const float4*)(team_emb + tv * 256 + col0);
            const float4* se = (const float4*)(ship_emb + (grow & 7) * 256 + col0);
#pragma unroll
            for (int q = 0; q < 8; q++) {
                float4 a = te[q], b = se[q];
                eb[q] = make_float4(a.x + b.x, a.y + b.y, a.z + b.z, a.w + b.w);
            }
        }
        uint32_t r[32];
        asm volatile("tcgen05.ld.sync.aligned.32x32b.x32.b32 "
            "{%0,%1,%2,%3,%4,%5,%6,%7,%8,%9,%10,%11,%12,%13,%14,%15,"
            "%16,%17,%18,%19,%20,%21,%22,%23,%24,%25,%26,%27,%28,%29,%30,%31}, [%32];"
            : "=r"(r[0]), "=r"(r[1]), "=r"(r[2]), "=r"(r[3]),
              "=r"(r[4]), "=r"(r[5]), "=r"(r[6]), "=r"(r[7]),
              "=r"(r[8]), "=r"(r[9]), "=r"(r[10]), "=r"(r[11]),
              "=r"(r[12]), "=r"(r[13]), "=r"(r[14]), "=r"(r[15]),
              "=r"(r[16]), "=r"(r[17]), "=r"(r[18]), "=r"(r[19]),
              "=r"(r[20]), "=r"(r[21]), "=r"(r[22]), "=r"(r[23]),
              "=r"(r[24]), "=r"(r[25]), "=r"(r[26]), "=r"(r[27]),
              "=r"(r[28]), "=r"(r[29]), "=r"(r[30]), "=r"(r[31])
            : "r"(tmem + lc0));
        asm volatile("tcgen05.wait::ld.sync.aligned;" ::: "memory");
        float f[32];
#pragma unroll
        for (int j = 0; j < 32; j++) {
            float v = __uint_as_float(r[j]) + bias[col0 + j];
            if (EMODE == 1) v += ((const float*)eb)[j];
            if (EMODE == 2) v += ((const float*)res)[j];
            if (RMSOUT) ss += v * v;
            f[j] = v;
        }
        if (COUT == 0) {
            float4* cp = (float4*)((float*)Cv + (size_t)grow * ldc + col0);
#pragma unroll
            for (int q = 0; q < 8; q++)
                cp[q] = make_float4(f[4 * q], f[4 * q + 1], f[4 * q + 2], f[4 * q + 3]);
        } else {
            __half* C = (__half*)Cv + (size_t)grow * ldc + col0;
#pragma unroll
            for (int q = 0; q < 4; q++) {
                __half2 h0 = __float22half2_rn(make_float2(f[8 * q], f[8 * q + 1]));
                __half2 h1 = __float22half2_rn(make_float2(f[8 * q + 2], f[8 * q + 3]));
                __half2 h2 = __float22half2_rn(make_float2(f[8 * q + 4], f[8 * q + 5]));
                __half2 h3 = __float22half2_rn(make_float2(f[8 * q + 6], f[8 * q + 7]));
                *(uint4*)(C + 8 * q) = make_uint4(*(uint32_t*)&h0, *(uint32_t*)&h1,
                                                  *(uint32_t*)&h2, *(uint32_t*)&h3);
            }
        }
    }
    if (RMSOUT) {
        float* ssred = (float*)(sm + AOFF + 16384 + 16);
        ssred[half * 128 + rowl] = ss;
        __syncthreads();
        if (tid < 128) {
            float tot = ssred[tid] + ssred[128 + tid];
            rsout[rowBase + tid] = rsqrtf(tot * (1.0f / 256.0f) + 1e-6f);
        }
        __syncthreads();
    }
    if (wid == 0)
        asm volatile("tcgen05.dealloc.cta_group::1.sync.aligned.b32 %0, %1;" :: "r"(tmem), "r"(NT * 128));
#endif
}

__global__ void __launch_bounds__(256) trunk_k(const float* __restrict__ pos,
                                               const float* __restrict__ vel,
                                               const float* __restrict__ tW1,
                                               const float* __restrict__ tb1) {
    __shared__ float W1s[384], b1s[64];
    __shared__ __align__(16) float Wcs[2048];
    __shared__ float bcs[32];
    __shared__ float ps[4][8][2], vs[4][8][2];
    const int tid = threadIdx.x;
    for (int i = tid; i < 384; i += 256) W1s[i] = tW1[i];
    for (int i = tid; i < 2048; i += 256) Wcs[i] = g_Wc[i];
    if (tid < 64) b1s[tid] = tb1[tid];
    if (tid < 32) bcs[tid] = g_bc[tid];
    if (tid < 64) {
        int sub = tid >> 4, a = (tid >> 1) & 7, cmp = tid & 1;
        int gi = ((blockIdx.x * 4 + sub) * 8 + a) * 2 + cmp;
        ps[sub][a][cmp] = pos[gi] * 1024.0f;
        vs[sub][a][cmp] = vel[gi];
    }
    __syncthreads();

    const int sub = tid >> 6, pair = tid & 63, i = pair >> 3, j = pair & 7;
    const int scene = blockIdx.x * 4 + sub;
    float rx = ps[sub][i][0] - ps[sub][j][0];
    float ry = ps[sub][i][1] - ps[sub][j][1];
    rx -= rintf(rx * (1.0f / 1024.0f)) * 1024.0f;
    ry -= rintf(ry * (1.0f / 1024.0f)) * 1024.0f;
    float rvx = vs[sub][i][0] - vs[sub][j][0];
    float rvy = vs[sub][i][1] - vs[sub][j][1];
    float dn = sqrtf(rx * rx + ry * ry + 1e-8f) * (1.0f / 1024.0f);
    float f0 = rx * (1.0f / 1024.0f), f1 = ry * (1.0f / 1024.0f);
    float f4 = dn, f5 = 1.0f / (1.0f + dn);

    unsigned long long acc[16];
#pragma unroll
    for (int t = 0; t < 16; t++) acc[t] = pk2(bcs[2 * t], bcs[2 * t + 1]);
    for (int k = 0; k < 64; k++) {
        float t1 = b1s[k] + f0 * W1s[k] + f1 * W1s[64 + k] + rvx * W1s[128 + k] +
                   rvy * W1s[192 + k] + f4 * W1s[256 + k] + f5 * W1s[320 + k];
        float sv = t1 / (1.0f + __expf(-t1));
        unsigned long long svd = dup2(sv);
        const unsigned long long* wc = (const unsigned long long*)&Wcs[k * 32];
#pragma unroll
        for (int t = 0; t < 16; t++) acc[t] = fma2(svd, wc[t], acc[t]);
    }
#pragma unroll
    for (int t = 0; t < 16; t++) {
        float2 p = unp2(acc[t]);
        int m0 = 2 * t, m1 = 2 * t + 1;
        g_bias[(((size_t)(m0 >> 3) * SCENES + scene) * 8 + (m0 & 7)) * 64 + pair] = p.x;
        g_bias[(((size_t)(m1 >> 3) * SCENES + scene) * 8 + (m1 & 7)) * 64 + pair] = p.y;
    }
}

__global__ void __launch_bounds__(384) head_k(const float* __restrict__ hW,
                                              const float* __restrict__ hb,
                                              float* __restrict__ out) {
    __shared__ float xs[32 * 256];
    __shared__ float ws[256 * 12];
    __shared__ float hbs[12];
    const int tid = threadIdx.x;
    const size_t tokBase = (size_t)blockIdx.x * 32;
    for (int i = tid; i < 3072; i += 384) ws[i] = hW[i];
    if (tid < 12) hbs[tid] = hb[tid];
    for (int i = tid; i < 8192; i += 384) xs[i] = g_x[tokBase * 256 + i];
    __syncthreads();
    const int t = tid / 12, c = tid - t * 12;
    float acc = hbs[c];
#pragma unroll 8
    for (int k = 0; k < 256; k++) acc += xs[t * 256 + k] * ws[k * 12 + c];
    out[(tokBase + t) * 12 + c] = acc;
}

extern "C" void kernel_launch(void* const* d_in, const int* in_sizes, int n_in,
                              void* d_out, int out_size) {
    const float* state = (const float*)d_in[0];
    const float* pos = (const float*)d_in[1];
    const float* vel = (const float*)d_in[2];
    const int* team_ids = (const int*)d_in[3];
    const unsigned char* alive = (const unsigned char*)d_in[4];
    const float* dead = (const float*)d_in[5];
    const float* enc_W1 = (const float*)d_in[6];
    const float* enc_b1 = (const float*)d_in[7];
    const float* enc_W2 = (const float*)d_in[8];
    const float* enc_b2 = (const float*)d_in[9];
    const float* team_emb = (const float*)d_in[10];
    const float* ship_emb = (const float*)d_in[11];
    const float* tW1 = (const float*)d_in[12];
    const float* tb1 = (const float*)d_in[13];
    const float* tW2 = (const float*)d_in[14];
    const float* tb2 = (const float*)d_in[15];
    const float* aW = (const float*)d_in[16];
    const float* ab = (const float*)d_in[17];
    const float* norm_w = (const float*)d_in[18];
    const float* Wq = (const float*)d_in[19];
    const float* bq = (const float*)d_in[20];
    const float* Wk = (const float*)d_in[21];
    const float* bk = (const float*)d_in[22];
    const float* Wv = (const float*)d_in[23];
    const float* bv = (const float*)d_in[24];
    const float* Wo = (const float*)d_in[25];
    const float* bo = (const float*)d_in[26];
    const float* head_W = (const float*)d_in[27];
    const float* head_b = (const float*)d_in[28];
    float* out = (float*)d_out;

    float *p_x, *p_rs, *p_bqkv, *p_bias;
    __half *p_qkv, *p_o, *p_blob;
    cudaGetSymbolAddress((void**)&p_x, g_x);
    cudaGetSymbolAddress((void**)&p_qkv, g_qkv);
    cudaGetSymbolAddress((void**)&p_o, g_o);
    cudaGetSymbolAddress((void**)&p_rs, g_rs);
    cudaGetSymbolAddress((void**)&p_blob, g_wblob);
    cudaGetSymbolAddress((void**)&p_bqkv, g_bqkv);
    cudaGetSymbolAddress((void**)&p_bias, g_bias);

    cudaFuncSetAttribute(mm_k<1, 0, 1, 1, 0, 0, 0, 2>, cudaFuncAttributeMaxDynamicSharedMemorySize, SMEMB2);
    cudaFuncSetAttribute(mm_k<0, 1, 0, 0, 1, 1, 0, 1>, cudaFuncAttributeMaxDynamicSharedMemorySize, SMEMB1);
    cudaFuncSetAttribute(mm_k<0, 0, 2, 1, 0, 0, 1, 2>, cudaFuncAttributeMaxDynamicSharedMemorySize, SMEMB2);

    detect_k<<<1, 256>>>(alive);
    wconv_k<<<4352, 256>>>(enc_W2, Wq, Wk, Wv, Wo, norm_w, p_blob);
    enc1_k<<<TOK / 32, 256>>>(state, alive, dead, enc_W1, enc_b1);
    mm_k<1, 0, 1, 1, 0, 0, 0, 2><<<dim3(1024, 1), 256, SMEMB2>>>(
        p_o, p_blob, 0, enc_b2, p_x, 256, nullptr, p_rs, team_emb, ship_emb, team_ids,
        nullptr, nullptr);

    packb_k<<<12, 256>>>(bq, bk, bv, p_bqkv);
    fold_k<<<1, 256>>>(tW2, aW, tb2, ab);
    trunk_k<<<SCENES / 4, 256>>>(pos, vel, tW1, tb1);

    for (int l = 0; l < NL; l++) {
        // qkv: NT=1, occ 4, grid (6 ntiles, 1024 row tiles)
        mm_k<0, 1, 0, 0, 1, 1, 0, 1><<<dim3(6, 1024), 256, SMEMB1>>>(
            p_x, p_blob, 2 + l * 8, p_bqkv + l * 768, p_qkv, 768, p_rs, nullptr,
            nullptr, nullptr, nullptr, nullptr, nullptr);
        mm_k<0, 0, 2, 1, 0, 0, 1, 2><<<dim3(1024, 1), 256, SMEMB2>>>(
            p_qkv, p_blob, 2 + l * 8 + 6, bo + l * 256, p_x, 256, nullptr, p_rs,
            nullptr, nullptr, nullptr, p_bias + (size_t)l * SCENES * 512, alive);
    }
    head_k<<<TOK / 32, 384>>>(head_W, head_b, out);
}

// round 17
// speedup vs baseline: 1.1583x; 1.1583x over previous
#include <cuda_runtime.h>
#include <cuda_bf16.h>
#include <cuda_fp16.h>
#include <cstdint>

#define TOK 131072
#define SCENES 16384
#define NL 4

#if !defined(__CUDA_ARCH__) || defined(__CUDA_ARCH_FEAT_SM103_ALL) || \
    defined(__CUDA_ARCH_FEAT_SM100_ALL) || defined(__CUDA_ARCH_FEAT_SM101_ALL) || \
    defined(__CUDA_ARCH_FEAT_SM110_ALL) || defined(__CUDA_ARCH_FEAT_SM120_ALL)
#define HAS_TC 1
#else
#define HAS_TC 0
#endif

__device__ float  g_x[(size_t)TOK * 256];
__device__ __half g_qkv[(size_t)TOK * 768];
__device__ __half g_o[(size_t)TOK * 256];
__device__ float  g_bias[(size_t)NL * SCENES * 8 * 64];
__device__ float  g_rs[TOK];
__device__ int    g_alive_u8;
__device__ __half g_wblob[(size_t)34 * 4 * 2 * 8192];   // swizzled fp16 hi/lo weights
__device__ float  g_Wc[64 * 32];
__device__ float  g_bc[32];
__device__ float  g_bqkv[NL * 768];

__device__ __forceinline__ unsigned long long fma2(unsigned long long a,
                                                   unsigned long long b,
                                                   unsigned long long c) {
    unsigned long long d;
    asm("fma.rn.f32x2 %0, %1, %2, %3;" : "=l"(d) : "l"(a), "l"(b), "l"(c));
    return d;
}
__device__ __forceinline__ unsigned long long dup2(float x) {
    unsigned long long r; asm("mov.b64 %0, {%1, %1};" : "=l"(r) : "f"(x)); return r;
}
__device__ __forceinline__ unsigned long long pk2(float a, float b) {
    unsigned long long r; asm("mov.b64 %0, {%1, %2};" : "=l"(r) : "f"(a), "f"(b)); return r;
}
__device__ __forceinline__ float2 unp2(unsigned long long v) {
    float2 r; asm("mov.b64 {%0, %1}, %2;" : "=f"(r.x), "=f"(r.y) : "l"(v)); return r;
}
__device__ __forceinline__ uint32_t smem_u32(const void* p) {
    uint32_t a;
    asm("{ .reg .u64 t; cvta.to.shared.u64 t, %1; cvt.u32.u64 %0, t; }" : "=r"(a) : "l"(p));
    return a;
}
__device__ __forceinline__ bool aget(const unsigned char* a, int i) {
    return g_alive_u8 ? (a[i] != 0) : (a[i * 4] != 0);
}
__device__ __forceinline__ uint32_t sw_off(int row, int kl) {
    uint32_t b = (row & 7) * 128 + kl * 2;
    b ^= (b >> 3) & 0x70;
    return (uint32_t)((row >> 3) * 1024) + b;
}
#define MMA_IDESC 0x8200010u   // f32 accum, f16 A/B, N=128, M=128

#if HAS_TC
#define MBAR_WAIT(mba, par) do { \
    uint32_t _m = (mba); uint32_t _p = (par); uint32_t _d; \
    asm volatile("{\n\t.reg .pred p;\n\tmbarrier.try_wait.parity.acquire.cta.shared::cta.b64 p, [%1], %2;\n\tselp.b32 %0, 1, 0, p;\n\t}" \
        : "=r"(_d) : "r"(_m), "r"(_p) : "memory"); \
    if (!_d) { \
        asm volatile("{\n\t.reg .pred P1;\n\tWL_%=:\n\tmbarrier.try_wait.parity.acquire.cta.shared::cta.b64 P1, [%0], %1, 0x989680;\n\t@P1 bra.uni WD_%=;\n\tbra.uni WL_%=;\n\tWD_%=:\n\t}" \
            :: "r"(_m), "r"(_p) : "memory"); \
    } } while (0)
#endif

__global__ void detect_k(const unsigned char* __restrict__ a) {
    __shared__ int any;
    if (threadIdx.x == 0) any = 0;
    __syncthreads();
    for (int i = threadIdx.x; i < 4096; i += 256)
        if ((i & 3) != 0 && a[i] != 0) any = 1;
    __syncthreads();
    if (threadIdx.x == 0) g_alive_u8 = any;
}

__global__ void __launch_bounds__(256) enc1_k(const float* __restrict__ state,
                                              const unsigned char* __restrict__ alive,
                                              const float* __restrict__ dead,
                                              const float* __restrict__ W1,
                                              const float* __restrict__ b1) {
    __shared__ float ss[32 * 16];
    const int tid = threadIdx.x;
    const int tokBase = blockIdx.x * 32;
#pragma unroll
    for (int r = 0; r < 2; r++) {
        int idx = tid * 2 + r;
        int t = idx >> 4, k = idx & 15;
        ss[idx] = aget(alive, tokBase + t) ? state[(size_t)(tokBase + t) * 16 + k] : dead[k];
    }
    __syncthreads();
    float w[16];
#pragma unroll
    for (int k = 0; k < 16; k++) w[k] = W1[k * 256 + tid];
    const float bc = b1[tid];
#pragma unroll 4
    for (int t = 0; t < 32; t++) {
        float a = bc;
#pragma unroll
        for (int k = 0; k < 16; k++) a += ss[t * 16 + k] * w[k];
        a = a / (1.0f + __expf(-a));
        g_o[(size_t)(tokBase + t) * 256 + tid] = __float2half(a);
    }
}

__global__ void __launch_bounds__(256) wconv_k(
    const float* __restrict__ encW2, const float* __restrict__ Wq,
    const float* __restrict__ Wk, const float* __restrict__ Wv,
    const float* __restrict__ Wo, const float* __restrict__ norm_w,
    __half* __restrict__ blob) {
    int gid = blockIdx.x * 256 + threadIdx.x;
    int region = gid >> 13;
    int r = gid & 8191;
    int nl = r >> 6, kl = r & 63;
    int tile = region >> 2, chunk = region & 3;
    int k = chunk * 64 + kl;
    const float* W; int n; float g = 1.0f;
    if (tile < 2) { W = encW2; n = tile * 128 + nl; }
    else {
        int t2 = tile - 2, l = t2 >> 3, j = t2 & 7;
        if (j < 6) {
            W = (j < 2 ? Wq : (j < 4 ? Wk : Wv)) + l * 65536;
            n = (j & 1) * 128 + nl;
            g = norm_w[l * 256 + k];
        } else { W = Wo + l * 65536; n = (j - 6) * 128 + nl; }
    }
    float w = W[k * 256 + n] * g;
    __half hi = __float2half_rn(w);
    __half lo = __float2half_rn(w - __half2float(hi));
    uint32_t b = (nl & 7) * 128 + kl * 2; b ^= (b >> 3) & 0x70;
    uint32_t eo = (uint32_t)((nl >> 3) * 512) + (b >> 1);
    size_t base = (size_t)region * 2 * 8192;
    blob[base + eo] = hi;
    blob[base + 8192 + eo] = lo;
}

__global__ void packb_k(const float* __restrict__ bq, const float* __restrict__ bk,
                        const float* __restrict__ bv, float* __restrict__ dst) {
    int gid = blockIdx.x * 256 + threadIdx.x;
    if (gid >= NL * 768) return;
    int l = gid / 768, c = gid - l * 768;
    float v = c < 256 ? bq[l * 256 + c] : (c < 512 ? bk[l * 256 + c - 256] : bv[l * 256 + c - 512]);
    dst[gid] = v;
}

__global__ void __launch_bounds__(256) fold_k(const float* __restrict__ tW2,
                                              const float* __restrict__ aW,
                                              const float* __restrict__ tb2,
                                              const float* __restrict__ ab) {
    int tid = threadIdx.x;
#pragma unroll
    for (int i = 0; i < 8; i++) {
        int idx = tid + i * 256;
        int k = idx >> 5, m = idx & 31, l = m >> 3, h = m & 7;
        float s = 0.f;
        for (int c = 0; c < 64; c++) s += tW2[k * 64 + c] * aW[(l * 64 + c) * 8 + h];
        g_Wc[idx] = s;
    }
    if (tid < 32) {
        int l = tid >> 3, h = tid & 7;
        float s = ab[tid];
        for (int c = 0; c < 64; c++) s += tb2[c] * aW[(l * 64 + c) * 8 + h];
        g_bc[tid] = s;
    }
}

// tcgen05 GEMM, fp16 A (single) x fp16 hi/lo B (2 passes). ATTN=1: fused attention A.
#define SMEMB 102400
template <int AIN, int AMODE, int EMODE, int RMSOUT, int COUT, int SWAP, int ATTN>
__global__ void __launch_bounds__(256, 2) mm_k(
    const void* __restrict__ Av, const __half* __restrict__ blob, int tileBase,
    const float* __restrict__ bias, void* __restrict__ Cv, int ldc,
    const float* __restrict__ rscale, float* __restrict__ rsout,
    const float* __restrict__ team_emb, const float* __restrict__ ship_emb,
    const int* __restrict__ team_ids,
    const float* __restrict__ abias, const unsigned char* __restrict__ alivep) {
#if HAS_TC
    extern __shared__ char dsm_raw[];
    char* sm = (char*)(((uintptr_t)dsm_raw + 1023) & ~(uintptr_t)1023);
    const uint32_t sbase = smem_u32(sm);
    const int tid = threadIdx.x, wid = tid >> 5, lane = tid & 31;
    const int rowTile = SWAP ? blockIdx.y : blockIdx.x;
    const int ntile = SWAP ? blockIdx.x : blockIdx.y;
    const int rowBase = rowTile * 128;
    const int coff = ntile * 256;
    const uint32_t ctrl = sbase + 81920;
    const uint32_t mbar = ctrl + 8;

    if (wid == 0) {
        asm volatile("tcgen05.alloc.cta_group::1.sync.aligned.shared::cta.b32 [%0], %1;"
                     :: "r"(ctrl), "r"(256) : "memory");
        asm volatile("tcgen05.relinquish_alloc_permit.cta_group::1.sync.aligned;");
    }
    if (tid == 0)
        asm volatile("mbarrier.init.shared.b64 [%0], %1;" :: "r"(mbar), "r"(1) : "memory");
    __syncthreads();
    const uint32_t tmem = *(volatile uint32_t*)(sm + 81920);

    const int arow = tid >> 1, klb = (tid & 1) * 32;
    float rsv = 1.0f;
    if (AMODE == 1) rsv = rscale[rowBase + arow];
    const float* Apf = (const float*)Av + (size_t)(rowBase + arow) * 256 + klb;
    const __half* Aph = (const __half*)Av + (size_t)(rowBase + arow) * 256 + klb;
    const int pairq = tid >> 3, sub = tid & 7;
    const int sc16 = pairq >> 1, hsel = pairq & 1;
    const int scene = rowTile * 16 + sc16;
    const int tok = scene * 8 + sub;
    const int shsrc = (lane & 24);

    for (int c = 0; c < 4; c++) {
        float4 av[8];
        uint4 ah[4];
        if (!ATTN) {
            if (AIN == 0) {
                const float4* ap4 = (const float4*)(Apf + c * 64);
#pragma unroll
                for (int i = 0; i < 8; i++) av[i] = ap4[i];
            } else {
                const uint4* ah4 = (const uint4*)(Aph + c * 64);
#pragma unroll
                for (int u = 0; u < 4; u++) ah[u] = ah4[u];
            }
        }
        if (c > 0) MBAR_WAIT(mbar, (c - 1) & 1);
#pragma unroll
        for (int r = 0; r < 4; r++) {
            int tile = tileBase + ntile * 2 + (r >> 1);
            const char* srcb = (const char*)(blob + (size_t)((tile * 4 + c) * 2 + (r & 1)) * 8192);
#pragma unroll
            for (int j = 0; j < 4; j++) {
                uint32_t d = sbase + (uint32_t)(r * 16384) + (uint32_t)((tid + j * 256) * 16);
                asm volatile("cp.async.cg.shared.global [%0], [%1], 16;"
                             :: "r"(d), "l"(srcb + (tid + j * 256) * 16) : "memory");
            }
        }
        asm volatile("cp.async.commit_group;" ::: "memory");
        if (ATTN) {
            const __half* bq = (const __half*)Av + (size_t)tok * 768 + c * 64 + hsel * 32;
            float a8[8];
            {
                uint32_t qu[16], ku[16];
#pragma unroll
                for (int u = 0; u < 4; u++) {
                    uint4 a = *(const uint4*)(bq + u * 8);
                    uint4 b = *(const uint4*)(bq + 256 + u * 8);
                    qu[4 * u] = a.x; qu[4 * u + 1] = a.y; qu[4 * u + 2] = a.z; qu[4 * u + 3] = a.w;
                    ku[4 * u] = b.x; ku[4 * u + 1] = b.y; ku[4 * u + 2] = b.z; ku[4 * u + 3] = b.w;
                }
                const float* bp = abias + (((size_t)scene * 8) + (2 * c + hsel)) * 64 + sub * 8;
                float4 b0 = *(const float4*)bp, b1 = *(const float4*)(bp + 4);
                float brow[8] = {b0.x, b0.y, b0.z, b0.w, b1.x, b1.y, b1.z, b1.w};
#pragma unroll
                for (int jj = 0; jj < 8; jj++) {
                    float s = 0.f;
                    int src = shsrc | jj;
#pragma unroll
                    for (int d = 0; d < 16; d++) {
                        uint32_t kw = __shfl_sync(0xffffffffu, ku[d], src);
                        float2 kf = __half22float2(*(__half2*)&kw);
                        float2 qf = __half22float2(*(__half2*)&qu[d]);
                        s += qf.x * kf.x + qf.y * kf.y;
                    }
                    a8[jj] = s * 0.17677669529663687f + brow[jj];
                    if (!aget(alivep, scene * 8 + jj)) a8[jj] = -1e9f;
                }
            }
            {
                float m = a8[0];
#pragma unroll
                for (int jj = 1; jj < 8; jj++) m = fmaxf(m, a8[jj]);
                float tot = 0.f;
#pragma unroll
                for (int jj = 0; jj < 8; jj++) { a8[jj] = __expf(a8[jj] - m); tot += a8[jj]; }
                float inv = 1.0f / tot;
#pragma unroll
                for (int jj = 0; jj < 8; jj++) a8[jj] *= inv;
            }
            const int row = sc16 * 8 + sub;
#pragma unroll
            for (int vh = 0; vh < 2; vh++) {
                uint32_t vu[8];
                const __half* bv = bq + 512 + vh * 16;
#pragma unroll
                for (int u = 0; u < 2; u++) {
                    uint4 d = *(const uint4*)(bv + u * 8);
                    vu[4 * u] = d.x; vu[4 * u + 1] = d.y; vu[4 * u + 2] = d.z; vu[4 * u + 3] = d.w;
                }
                float o16[16];
#pragma unroll
                for (int d = 0; d < 16; d++) o16[d] = 0.f;
#pragma unroll
                for (int jj = 0; jj < 8; jj++) {
                    float a = a8[jj];
                    int src = shsrc | jj;
#pragma unroll
                    for (int d = 0; d < 8; d++) {
                        uint32_t vw = __shfl_sync(0xffffffffu, vu[d], src);
                        float2 vf = __half22float2(*(__half2*)&vw);
                        o16[2 * d] += a * vf.x;
                        o16[2 * d + 1] += a * vf.y;
                    }
                }
#pragma unroll
                for (int d8 = 0; d8 < 2; d8++) {
                    int kl = hsel * 32 + vh * 16 + d8 * 8;
                    __half2 p0 = __float22half2_rn(make_float2(o16[8 * d8], o16[8 * d8 + 1]));
                    __half2 p1 = __float22half2_rn(make_float2(o16[8 * d8 + 2], o16[8 * d8 + 3]));
                    __half2 p2 = __float22half2_rn(make_float2(o16[8 * d8 + 4], o16[8 * d8 + 5]));
                    __half2 p3 = __float22half2_rn(make_float2(o16[8 * d8 + 6], o16[8 * d8 + 7]));
                    *(uint4*)(sm + 65536 + sw_off(row, kl)) =
                        make_uint4(*(uint32_t*)&p0, *(uint32_t*)&p1, *(uint32_t*)&p2, *(uint32_t*)&p3);
                }
            }
        } else if (AIN == 1) {
#pragma unroll
            for (int u = 0; u < 4; u++)
                *(uint4*)(sm + 65536 + sw_off(arow, klb + u * 8)) = ah[u];
        } else {
#pragma unroll
            for (int i = 0; i < 4; i++) {
                float4 lo4 = av[2 * i], hi4 = av[2 * i + 1];
                __half2 p0 = __float22half2_rn(make_float2(lo4.x * rsv, lo4.y * rsv));
                __half2 p1 = __float22half2_rn(make_float2(lo4.z * rsv, lo4.w * rsv));
                __half2 p2 = __float22half2_rn(make_float2(hi4.x * rsv, hi4.y * rsv));
                __half2 p3 = __float22half2_rn(make_float2(hi4.z * rsv, hi4.w * rsv));
                *(uint4*)(sm + 65536 + sw_off(arow, klb + i * 8)) =
                    make_uint4(*(uint32_t*)&p0, *(uint32_t*)&p1, *(uint32_t*)&p2, *(uint32_t*)&p3);
            }
        }
        asm volatile("cp.async.wait_group 0;" ::: "memory");
        asm volatile("fence.proxy.async.shared::cta;" ::: "memory");
        __syncthreads();
        if (wid == 0) {
            asm volatile("tcgen05.fence::after_thread_sync;" ::: "memory");
            uint32_t is_el;
            asm volatile("{\n\t.reg .pred p;\n\telect.sync _|p, 0xFFFFFFFF;\n\tselp.b32 %0, 1, 0, p;\n\t}" : "=r"(is_el));
            if (is_el) {
                const uint64_t DBASE = (2ull << 61) | (1ull << 46) | (64ull << 32) | (1ull << 16);
                uint64_t dA = DBASE | (((uint64_t)((sbase + 65536) >> 4)) & 0x3FFF);
#pragma unroll
                for (int pass = 0; pass < 2; pass++) {
#pragma unroll
                    for (int t = 0; t < 2; t++) {
                        uint64_t bd = DBASE | (((uint64_t)((sbase + (t * 2 + pass) * 16384) >> 4)) & 0x3FFF);
#pragma unroll
                        for (int ks = 0; ks < 4; ks++) {
                            uint32_t en = !(c == 0 && pass == 0 && ks == 0) ? 1u : 0u;
                            asm volatile(
                                "{\n\t.reg .pred p;\n\tsetp.ne.u32 p, %4, 0;\n\t"
                                "tcgen05.mma.cta_group::1.kind::f16 [%0], %1, %2, %3, {%5,%5,%5,%5}, p;\n\t}"
                                :: "r"(tmem + t * 128), "l"(dA + ks * 2), "l"(bd + ks * 2),
                                   "r"(MMA_IDESC), "r"(en), "r"(0u) : "memory");
                        }
                    }
                }
                asm volatile("tcgen05.commit.cta_group::1.mbarrier::arrive::one.shared::cluster.b64 [%0];"
                             :: "r"(mbar) : "memory");
            }
        }
    }
    MBAR_WAIT(mbar, 1);
    asm volatile("tcgen05.fence::after_thread_sync;" ::: "memory");

    const int ew = wid & 3, half = wid >> 2;
    const int rowl = ew * 32 + lane;
    const int grow = rowBase + rowl;
    float ss = 0.f;
    int tv = 0;
    if (EMODE == 1) tv = team_ids[grow];
    for (int it = 0; it < 4; it++) {
        const int lc0 = half * 128 + it * 32;
        const int col0 = coff + lc0;
        float4 res[8];
        if (EMODE == 2) {
            const float4* rp = (const float4*)((const float*)Cv + (size_t)grow * ldc + col0);
#pragma unroll
            for (int q = 0; q < 8; q++) res[q] = rp[q];
        }
        float4 eb[8];
        if (EMODE == 1) {
            const float4* te = (const float4*)(team_emb + tv * 256 + col0);
            const float4* se = (const float4*)(ship_emb + (grow & 7) * 256 + col0);
#pragma unroll
            for (int q = 0; q < 8; q++) {
                float4 a = te[q], b = se[q];
                eb[q] = make_float4(a.x + b.x, a.y + b.y, a.z + b.z, a.w + b.w);
            }
        }
        uint32_t r[32];
        asm volatile("tcgen05.ld.sync.aligned.32x32b.x32.b32 "
            "{%0,%1,%2,%3,%4,%5,%6,%7,%8,%9,%10,%11,%12,%13,%14,%15,"
            "%16,%17,%18,%19,%20,%21,%22,%23,%24,%25,%26,%27,%28,%29,%30,%31}, [%32];"
            : "=r"(r[0]), "=r"(r[1]), "=r"(r[2]), "=r"(r[3]),
              "=r"(r[4]), "=r"(r[5]), "=r"(r[6]), "=r"(r[7]),
              "=r"(r[8]), "=r"(r[9]), "=r"(r[10]), "=r"(r[11]),
              "=r"(r[12]), "=r"(r[13]), "=r"(r[14]), "=r"(r[15]),
              "=r"(r[16]), "=r"(r[17]), "=r"(r[18]), "=r"(r[19]),
              "=r"(r[20]), "=r"(r[21]), "=r"(r[22]), "=r"(r[23]),
              "=r"(r[24]), "=r"(r[25]), "=r"(r[26]), "=r"(r[27]),
              "=r"(r[28]), "=r"(r[29]), "=r"(r[30]), "=r"(r[31])
            : "r"(tmem + lc0));
        asm volatile("tcgen05.wait::ld.sync.aligned;" ::: "memory");
        float f[32];
#pragma unroll
        for (int j = 0; j < 32; j++) {
            float v = __uint_as_float(r[j]) + bias[col0 + j];
            if (EMODE == 1) v += ((const float*)eb)[j];
            if (EMODE == 2) v += ((const float*)res)[j];
            if (RMSOUT) ss += v * v;
            f[j] = v;
        }
        if (COUT == 0) {
            float4* cp = (float4*)((float*)Cv + (size_t)grow * ldc + col0);
#pragma unroll
            for (int q = 0; q < 8; q++)
                cp[q] = make_float4(f[4 * q], f[4 * q + 1], f[4 * q + 2], f[4 * q + 3]);
        } else {
            __half* C = (__half*)Cv + (size_t)grow * ldc + col0;
#pragma unroll
            for (int q = 0; q < 4; q++) {
                __half2 h0 = __float22half2_rn(make_float2(f[8 * q], f[8 * q + 1]));
                __half2 h1 = __float22half2_rn(make_float2(f[8 * q + 2], f[8 * q + 3]));
                __half2 h2 = __float22half2_rn(make_float2(f[8 * q + 4], f[8 * q + 5]));
                __half2 h3 = __float22half2_rn(make_float2(f[8 * q + 6], f[8 * q + 7]));
                *(uint4*)(C + 8 * q) = make_uint4(*(uint32_t*)&h0, *(uint32_t*)&h1,
                                                  *(uint32_t*)&h2, *(uint32_t*)&h3);
            }
        }
    }
    if (RMSOUT) {
        float* ssred = (float*)(sm + 81936);
        ssred[half * 128 + rowl] = ss;
        __syncthreads();
        if (tid < 128) {
            float tot = ssred[tid] + ssred[128 + tid];
            rsout[rowBase + tid] = rsqrtf(tot * (1.0f / 256.0f) + 1e-6f);
        }
        __syncthreads();
    }
    if (wid == 0)
        asm volatile("tcgen05.dealloc.cta_group::1.sync.aligned.b32 %0, %1;" :: "r"(tmem), "r"(256));
#endif
}

__global__ void __launch_bounds__(256) trunk_k(const float* __restrict__ pos,
                                               const float* __restrict__ vel,
                                               const float* __restrict__ tW1,
                                               const float* __restrict__ tb1) {
    __shared__ float W1s[384], b1s[64];
    __shared__ __align__(16) float Wcs[2048];
    __shared__ float bcs[32];
    __shared__ float ps[4][8][2], vs[4][8][2];
    const int tid = threadIdx.x;
    for (int i = tid; i < 384; i += 256) W1s[i] = tW1[i];
    for (int i = tid; i < 2048; i += 256) Wcs[i] = g_Wc[i];
    if (tid < 64) b1s[tid] = tb1[tid];
    if (tid < 32) bcs[tid] = g_bc[tid];
    if (tid < 64) {
        int sub = tid >> 4, a = (tid >> 1) & 7, cmp = tid & 1;
        int gi = ((blockIdx.x * 4 + sub) * 8 + a) * 2 + cmp;
        ps[sub][a][cmp] = pos[gi] * 1024.0f;
        vs[sub][a][cmp] = vel[gi];
    }
    __syncthreads();

    const int sub = tid >> 6, pair = tid & 63, i = pair >> 3, j = pair & 7;
    const int scene = blockIdx.x * 4 + sub;
    float rx = ps[sub][i][0] - ps[sub][j][0];
    float ry = ps[sub][i][1] - ps[sub][j][1];
    rx -= rintf(rx * (1.0f / 1024.0f)) * 1024.0f;
    ry -= rintf(ry * (1.0f / 1024.0f)) * 1024.0f;
    float rvx = vs[sub][i][0] - vs[sub][j][0];
    float rvy = vs[sub][i][1] - vs[sub][j][1];
    float dn = sqrtf(rx * rx + ry * ry + 1e-8f) * (1.0f / 1024.0f);
    float f0 = rx * (1.0f / 1024.0f), f1 = ry * (1.0f / 1024.0f);
    float f4 = dn, f5 = 1.0f / (1.0f + dn);

    unsigned long long acc[16];
#pragma unroll
    for (int t = 0; t < 16; t++) acc[t] = pk2(bcs[2 * t], bcs[2 * t + 1]);
    for (int k = 0; k < 64; k++) {
        float t1 = b1s[k] + f0 * W1s[k] + f1 * W1s[64 + k] + rvx * W1s[128 + k] +
                   rvy * W1s[192 + k] + f4 * W1s[256 + k] + f5 * W1s[320 + k];
        float sv = t1 / (1.0f + __expf(-t1));
        unsigned long long svd = dup2(sv);
        const unsigned long long* wc = (const unsigned long long*)&Wcs[k * 32];
#pragma unroll
        for (int t = 0; t < 16; t++) acc[t] = fma2(svd, wc[t], acc[t]);
    }
#pragma unroll
    for (int t = 0; t < 16; t++) {
        float2 p = unp2(acc[t]);
        int m0 = 2 * t, m1 = 2 * t + 1;
        g_bias[(((size_t)(m0 >> 3) * SCENES + scene) * 8 + (m0 & 7)) * 64 + pair] = p.x;
        g_bias[(((size_t)(m1 >> 3) * SCENES + scene) * 8 + (m1 & 7)) * 64 + pair] = p.y;
    }
}

__global__ void __launch_bounds__(384) head_k(const float* __restrict__ hW,
                                              const float* __restrict__ hb,
                                              float* __restrict__ out) {
    __shared__ float xs[32 * 256];
    __shared__ float ws[256 * 12];
    __shared__ float hbs[12];
    const int tid = threadIdx.x;
    const size_t tokBase = (size_t)blockIdx.x * 32;
    for (int i = tid; i < 3072; i += 384) ws[i] = hW[i];
    if (tid < 12) hbs[tid] = hb[tid];
    for (int i = tid; i < 8192; i += 384) xs[i] = g_x[tokBase * 256 + i];
    __syncthreads();
    const int t = tid / 12, c = tid - t * 12;
    float acc = hbs[c];
#pragma unroll 8
    for (int k = 0; k < 256; k++) acc += xs[t * 256 + k] * ws[k * 12 + c];
    out[(tokBase + t) * 12 + c] = acc;
}

extern "C" void kernel_launch(void* const* d_in, const int* in_sizes, int n_in,
                              void* d_out, int out_size) {
    const float* state = (const float*)d_in[0];
    const float* pos = (const float*)d_in[1];
    const float* vel = (const float*)d_in[2];
    const int* team_ids = (const int*)d_in[3];
    const unsigned char* alive = (const unsigned char*)d_in[4];
    const float* dead = (const float*)d_in[5];
    const float* enc_W1 = (const float*)d_in[6];
    const float* enc_b1 = (const float*)d_in[7];
    const float* enc_W2 = (const float*)d_in[8];
    const float* enc_b2 = (const float*)d_in[9];
    const float* team_emb = (const float*)d_in[10];
    const float* ship_emb = (const float*)d_in[11];
    const float* tW1 = (const float*)d_in[12];
    const float* tb1 = (const float*)d_in[13];
    const float* tW2 = (const float*)d_in[14];
    const float* tb2 = (const float*)d_in[15];
    const float* aW = (const float*)d_in[16];
    const float* ab = (const float*)d_in[17];
    const float* norm_w = (const float*)d_in[18];
    const float* Wq = (const float*)d_in[19];
    const float* bq = (const float*)d_in[20];
    const float* Wk = (const float*)d_in[21];
    const float* bk = (const float*)d_in[22];
    const float* Wv = (const float*)d_in[23];
    const float* bv = (const float*)d_in[24];
    const float* Wo = (const float*)d_in[25];
    const float* bo = (const float*)d_in[26];
    const float* head_W = (const float*)d_in[27];
    const float* head_b = (const float*)d_in[28];
    float* out = (float*)d_out;

    float *p_x, *p_rs, *p_bqkv, *p_bias;
    __half *p_qkv, *p_o, *p_blob;
    cudaGetSymbolAddress((void**)&p_x, g_x);
    cudaGetSymbolAddress((void**)&p_qkv, g_qkv);
    cudaGetSymbolAddress((void**)&p_o, g_o);
    cudaGetSymbolAddress((void**)&p_rs, g_rs);
    cudaGetSymbolAddress((void**)&p_blob, g_wblob);
    cudaGetSymbolAddress((void**)&p_bqkv, g_bqkv);
    cudaGetSymbolAddress((void**)&p_bias, g_bias);

    cudaFuncSetAttribute(mm_k<1, 0, 1, 1, 0, 0, 0>, cudaFuncAttributeMaxDynamicSharedMemorySize, SMEMB);
    cudaFuncSetAttribute(mm_k<0, 1, 0, 0, 1, 1, 0>, cudaFuncAttributeMaxDynamicSharedMemorySize, SMEMB);
    cudaFuncSetAttribute(mm_k<0, 0, 2, 1, 0, 0, 1>, cudaFuncAttributeMaxDynamicSharedMemorySize, SMEMB);

    detect_k<<<1, 256>>>(alive);
    wconv_k<<<4352, 256>>>(enc_W2, Wq, Wk, Wv, Wo, norm_w, p_blob);
    enc1_k<<<TOK / 32, 256>>>(state, alive, dead, enc_W1, enc_b1);
    mm_k<1, 0, 1, 1, 0, 0, 0><<<dim3(1024, 1), 256, SMEMB>>>(
        p_o, p_blob, 0, enc_b2, p_x, 256, nullptr, p_rs, team_emb, ship_emb, team_ids,
        nullptr, nullptr);

    packb_k<<<12, 256>>>(bq, bk, bv, p_bqkv);
    fold_k<<<1, 256>>>(tW2, aW, tb2, ab);
    trunk_k<<<SCENES / 4, 256>>>(pos, vel, tW1, tb1);

    for (int l = 0; l < NL; l++) {
        mm_k<0, 1, 0, 0, 1, 1, 0><<<dim3(3, 1024), 256, SMEMB>>>(
            p_x, p_blob, 2 + l * 8, p_bqkv + l * 768, p_qkv, 768, p_rs, nullptr,
            nullptr, nullptr, nullptr, nullptr, nullptr);
        mm_k<0, 0, 2, 1, 0, 0, 1><<<dim3(1024, 1), 256, SMEMB>>>(
            p_qkv, p_blob, 2 + l * 8 + 6, bo + l * 256, p_x, 256, nullptr, p_rs,
            nullptr, nullptr, nullptr, p_bias + (size_t)l * SCENES * 512, alive);
    }
    head_k<<<TOK / 32, 384>>>(head_W, head_b, out);
}